// round 10
// baseline (speedup 1.0000x reference)
#include <cuda_runtime.h>
#include <cstdint>

// ---------------------------------------------------------------------------
// GeneratorNetwork: 512-step 2-layer LSTM (B=4096, H=512) + MDN head.
//   * idea = tanh(latent @ W_unpack^T + b) precomputed once.
//   * base1 = idea @ W_ih1[:, :512]^T + b_ih1 + b_hh1 precomputed once
//     (x = [idea, prev], prev = [angles, 0] -> rank-1 update in epilogue).
//   * ONE persistent kernel runs all 512 steps (software grid barrier) to
//     keep the CUDA graph tiny (5 nodes) -- fixes the 4MB graph-upload leak
//     and removes per-launch wave quantization via dynamic tile scheduling.
//   * TF32 tensor-core GEMMs with fused LSTM cell epilogues; gate weights
//     pre-interleaved (n' = unit*4 + gate); h1/h2 ping-pong.
// ---------------------------------------------------------------------------

#define BATCH 4096
#define RNN   512
#define CODE  512
#define GATES 2048
#define SEG   512
#define NCTA  148

// ---------------- device state (no cudaMalloc allowed) --------------------
__device__ __align__(256) float g_idea [BATCH * CODE];
__device__ __align__(256) float g_base1[BATCH * GATES];
__device__ __align__(256) float g_h1[2][BATCH * RNN];
__device__ __align__(256) float g_c1   [BATCH * RNN];
__device__ __align__(256) float g_h2[2][BATCH * RNN];
__device__ __align__(256) float g_c2   [BATCH * RNN];
__device__ __align__(256) float g_angles[BATCH];
__device__ __align__(256) float g_Wih1r[GATES * RNN];      // interleaved, tf32-rounded
__device__ __align__(256) float g_Whh1r[GATES * RNN];
__device__ __align__(256) float g_W2r  [GATES * 1024];     // [W_ih2 | W_hh2], K=1024
__device__ __align__(256) float g_wprev1[GATES];           // W_ih1[:,512], interleaved
__device__ __align__(256) float g_bias1[GATES];            // b_ih1+b_hh1, interleaved
__device__ __align__(256) float g_bias2[GATES];            // b_ih2+b_hh2, interleaved
__device__ __align__(256) float g_Whead[15 * RNN];         // [mix(5); mu(5); var(5)]
__device__ __align__(256) float g_bhead[16];
__device__ int g_bar;                                      // global barrier (monotonic)
__device__ int g_ctrs[2 * SEG];                            // per-phase tile counters

// ---------------- helpers --------------------------------------------------
__device__ __forceinline__ float tf32r(float x) {
    uint32_t u;
    asm("cvt.rna.tf32.f32 %0, %1;\n" : "=r"(u) : "f"(x));
    return __uint_as_float(u);
}

__device__ __forceinline__ void cp16(float* dst, const float* src) {
    uint32_t d = (uint32_t)__cvta_generic_to_shared(dst);
    asm volatile("cp.async.cg.shared.global [%0], [%1], 16;\n" :: "r"(d), "l"(src));
}

__device__ __forceinline__ float sigmoid_f(float x) {
    return 1.0f / (1.0f + __expf(-x));
}
__device__ __forceinline__ float tanh_f(float x) {
    x = fminf(fmaxf(x, -15.f), 15.f);
    float e = __expf(2.f * x);
    return (e - 1.f) / (e + 1.f);
}

// software grid barrier (all 148 CTAs co-resident: 1 CTA/SM by smem usage)
__device__ __forceinline__ void gsync(int& epoch) {
    __syncthreads();
    if (threadIdx.x == 0) {
        int target = (++epoch) * (int)gridDim.x;
        __threadfence();
        atomicAdd(&g_bar, 1);
        int v;
        do {
            asm volatile("ld.acquire.gpu.global.s32 %0, [%1];"
                         : "=r"(v) : "l"(&g_bar));
        } while (v < target);
    }
    __syncthreads();
}

// ---------------- init + reorder -------------------------------------------
__global__ void zero_kernel() {
    size_t i = (size_t)blockIdx.x * blockDim.x + threadIdx.x;
    if (i < (size_t)BATCH * RNN) {
        g_h1[0][i] = 0.f; g_h2[0][i] = 0.f;
        g_c1[i]    = 0.f; g_c2[i]    = 0.f;
    }
    if (i < BATCH) g_angles[i] = 0.f;
    if (i < 2 * SEG) g_ctrs[i] = 0;
    if (i == 0) g_bar = 0;
}

__global__ void reorder_kernel(
    const float* __restrict__ W_ih1, const float* __restrict__ W_hh1,
    const float* __restrict__ b_ih1, const float* __restrict__ b_hh1,
    const float* __restrict__ W_ih2, const float* __restrict__ W_hh2,
    const float* __restrict__ b_ih2, const float* __restrict__ b_hh2,
    const float* __restrict__ W_mu,  const float* __restrict__ b_mu,
    const float* __restrict__ W_var, const float* __restrict__ b_var,
    const float* __restrict__ W_mix, const float* __restrict__ b_mix)
{
    int np = blockIdx.x;          // interleaved gate index 0..2047
    int k  = threadIdx.x;         // 0..511
    int gate = np & 3, unit = np >> 2;
    int n = gate * 512 + unit;    // original row in the 4*RNN weight matrices

    g_Wih1r[np * 512 + k]        = tf32r(W_ih1[n * 514 + k]);   // W_ih1 is [2048, 514]
    g_Whh1r[np * 512 + k]        = tf32r(W_hh1[n * 512 + k]);
    g_W2r  [np * 1024 + k]       = tf32r(W_ih2[n * 512 + k]);
    g_W2r  [np * 1024 + 512 + k] = tf32r(W_hh2[n * 512 + k]);

    if (k == 0) {
        g_wprev1[np] = W_ih1[n * 514 + 512];
        g_bias1[np]  = b_ih1[n] + b_hh1[n];
        g_bias2[np]  = b_ih2[n] + b_hh2[n];
    }
    if (np < 15) {
        const float* src = (np < 5) ? (W_mix + np * 512)
                         : (np < 10) ? (W_mu + (np - 5) * 512)
                                     : (W_var + (np - 10) * 512);
        g_Whead[np * 512 + k] = src[k];
        if (k == 0)
            g_bhead[np] = (np < 5) ? b_mix[np] : (np < 10) ? b_mu[np - 5] : b_var[np - 10];
    }
}

// ---------------- TF32 GEMM tile with fused epilogues -----------------------
// C[4096, N] = A[4096, K] @ Bw[N, K]^T (NT, both K-contiguous)
// modes: 0=idea(tanh), 1=base1(+bias), 2=LSTM1 fused, 3=LSTM2 fused (K=1024)
#define BM 128
#define BN 128
#define BK 32
#define STG 3
#define ASTR 36
#define STAGE_FLOATS (2 * 128 * ASTR)   // 9216 floats per stage (A+B)

__device__ void gemm_tile(int mode, int pp,
                          const float* __restrict__ xA,
                          const float* __restrict__ xB,
                          const float* __restrict__ xbias,
                          int m0, int n0, float* smem)
{
    const int tid  = threadIdx.x;
    const int lane = tid & 31;
    const int warp = tid >> 5;
    const int wm   = warp & 3;     // 4 warps along M (32 rows each)
    const int wn   = warp >> 2;    // 2 warps along N (64 cols each)

    const float* A0; const float* A1 = nullptr; const float* Bw;
    int K;
    if      (mode == 0) { A0 = xA;           Bw = xB;       K = 512;  }
    else if (mode == 1) { A0 = g_idea;       Bw = g_Wih1r;  K = 512;  }
    else if (mode == 2) { A0 = g_h1[pp];     Bw = g_Whh1r;  K = 512;  }
    else                { A0 = g_h1[pp ^ 1]; A1 = g_h2[pp]; Bw = g_W2r; K = 1024; }
    const int KT = K / BK;

    float acc[2][8][4];
    #pragma unroll
    for (int a = 0; a < 2; ++a)
        #pragma unroll
        for (int b = 0; b < 8; ++b)
            #pragma unroll
            for (int c = 0; c < 4; ++c) acc[a][b][c] = 0.f;

    auto load_tile = [&](int buf, int kt) {
        const int k0 = kt * BK;
        const float* Asrc = A0; int kk = k0;
        if (A1 != nullptr && k0 >= 512) { Asrc = A1; kk = k0 - 512; }
        float* as = smem + buf * STAGE_FLOATS;
        float* bs = as + 128 * ASTR;
        #pragma unroll
        for (int i = 0; i < 4; ++i) {
            int cid = tid + 256 * i;
            int row = cid >> 3;
            int c4  = (cid & 7) << 2;
            cp16(&as[row * ASTR + c4], &Asrc[(size_t)(m0 + row) * 512 + kk + c4]);
        }
        #pragma unroll
        for (int i = 0; i < 4; ++i) {
            int cid = tid + 256 * i;
            int row = cid >> 3;
            int c4  = (cid & 7) << 2;
            cp16(&bs[row * ASTR + c4], &Bw[(size_t)(n0 + row) * K + k0 + c4]);
        }
    };

    auto compute = [&](int buf) {
        const float* as = smem + buf * STAGE_FLOATS;
        const float* bs = as + 128 * ASTR;
        #pragma unroll
        for (int ks = 0; ks < 4; ++ks) {
            const int kb = ks * 8 + (lane & 3);
            uint32_t af[2][4];
            #pragma unroll
            for (int tm = 0; tm < 2; ++tm) {
                int r = wm * 32 + tm * 16 + (lane >> 2);
                af[tm][0] = __float_as_uint(as[r * ASTR + kb]);
                af[tm][1] = __float_as_uint(as[(r + 8) * ASTR + kb]);
                af[tm][2] = __float_as_uint(as[r * ASTR + kb + 4]);
                af[tm][3] = __float_as_uint(as[(r + 8) * ASTR + kb + 4]);
            }
            uint32_t bf[8][2];
            #pragma unroll
            for (int tn = 0; tn < 8; ++tn) {
                int r = wn * 64 + tn * 8 + (lane >> 2);
                bf[tn][0] = __float_as_uint(bs[r * ASTR + kb]);
                bf[tn][1] = __float_as_uint(bs[r * ASTR + kb + 4]);
            }
            #pragma unroll
            for (int tm = 0; tm < 2; ++tm)
                #pragma unroll
                for (int tn = 0; tn < 8; ++tn)
                    asm volatile(
                        "mma.sync.aligned.m16n8k8.row.col.f32.tf32.tf32.f32 "
                        "{%0,%1,%2,%3},{%4,%5,%6,%7},{%8,%9},{%0,%1,%2,%3};\n"
                        : "+f"(acc[tm][tn][0]), "+f"(acc[tm][tn][1]),
                          "+f"(acc[tm][tn][2]), "+f"(acc[tm][tn][3])
                        : "r"(af[tm][0]), "r"(af[tm][1]), "r"(af[tm][2]), "r"(af[tm][3]),
                          "r"(bf[tn][0]), "r"(bf[tn][1]));
        }
    };

    // 3-stage cp.async pipeline
    #pragma unroll
    for (int s = 0; s < STG - 1; ++s) {
        load_tile(s, s);
        asm volatile("cp.async.commit_group;\n");
    }
    asm volatile("cp.async.wait_group %0;\n" :: "n"(STG - 2));
    __syncthreads();

    for (int kt = 0; kt < KT; ++kt) {
        int nk = kt + STG - 1;
        if (nk < KT) load_tile(nk % STG, nk);
        asm volatile("cp.async.commit_group;\n");
        compute(kt % STG);
        asm volatile("cp.async.wait_group %0;\n" :: "n"(STG - 2));
        __syncthreads();
    }
    asm volatile("cp.async.wait_group 0;\n");

    // ---- epilogue: park accumulators in smem, then fused math -------------
    float* gs = smem;   // 128 x 132 f32 tile reusing pipeline smem
    #pragma unroll
    for (int tm = 0; tm < 2; ++tm) {
        #pragma unroll
        for (int tn = 0; tn < 8; ++tn) {
            int r = wm * 32 + tm * 16 + (lane >> 2);
            int c = wn * 64 + tn * 8 + ((lane & 3) << 1);
            gs[r * 132 + c]           = acc[tm][tn][0];
            gs[r * 132 + c + 1]       = acc[tm][tn][1];
            gs[(r + 8) * 132 + c]     = acc[tm][tn][2];
            gs[(r + 8) * 132 + c + 1] = acc[tm][tn][3];
        }
    }
    __syncthreads();

    #pragma unroll 4
    for (int i = 0; i < 16; ++i) {
        int t   = i * 256 + tid;
        int row = t >> 5, q = t & 31;
        int b   = m0 + row;
        int np  = n0 + (q << 2);
        float4 v = *(float4*)&gs[row * 132 + (q << 2)];

        if (mode == 0) {
            float4 bb = *(const float4*)&xbias[np];
            float4 o;
            o.x = tf32r(tanh_f(v.x + bb.x));
            o.y = tf32r(tanh_f(v.y + bb.y));
            o.z = tf32r(tanh_f(v.z + bb.z));
            o.w = tf32r(tanh_f(v.w + bb.w));
            *(float4*)&g_idea[(size_t)b * 512 + np] = o;
        } else if (mode == 1) {
            float4 bb = *(const float4*)&g_bias1[np];
            v.x += bb.x; v.y += bb.y; v.z += bb.z; v.w += bb.w;
            *(float4*)&g_base1[(size_t)b * 2048 + np] = v;
        } else {
            float gi, gf, gg, go;
            float* cbuf; float* hout;
            if (mode == 2) {
                float4 bb = *(const float4*)&g_base1[(size_t)b * 2048 + np];
                float4 wp = *(const float4*)&g_wprev1[np];
                float ang = g_angles[b];
                gi = v.x + bb.x + ang * wp.x;
                gf = v.y + bb.y + ang * wp.y;
                gg = v.z + bb.z + ang * wp.z;
                go = v.w + bb.w + ang * wp.w;
                cbuf = g_c1; hout = g_h1[pp ^ 1];
            } else {
                float4 bb = *(const float4*)&g_bias2[np];
                gi = v.x + bb.x; gf = v.y + bb.y;
                gg = v.z + bb.z; go = v.w + bb.w;
                cbuf = g_c2; hout = g_h2[pp ^ 1];
            }
            int u = np >> 2;                       // global unit index
            size_t ci = (size_t)b * 512 + u;
            float cold = cbuf[ci];
            float si = sigmoid_f(gi);
            float sf = sigmoid_f(gf);
            float so = sigmoid_f(go);
            float cn = sf * cold + si * tanh_f(gg);
            cbuf[ci] = cn;
            hout[ci] = tf32r(so * tanh_f(cn));
        }
    }
    __syncthreads();
}

__global__ void __launch_bounds__(256, 1)
gemm_kernel(int mode, int pp,
            const float* __restrict__ xA,
            const float* __restrict__ xB,
            const float* __restrict__ xbias)
{
    extern __shared__ float smem[];
    gemm_tile(mode, pp, xA, xB, xbias, blockIdx.y * BM, blockIdx.x * BN, smem);
}

// ---------------- MDN head: one warp per batch row --------------------------
__device__ __forceinline__ void head_row(const float* __restrict__ eps,
                                         float* __restrict__ out,
                                         int s, int hp, int gw, int lane)
{
    const float* h = &g_h2[hp][(size_t)gw * RNN];

    float accv[15];
    #pragma unroll
    for (int j = 0; j < 15; ++j) accv[j] = 0.f;
    #pragma unroll
    for (int i = 0; i < 16; ++i) {
        float hv = h[lane + 32 * i];
        #pragma unroll
        for (int j = 0; j < 15; ++j)
            accv[j] += hv * g_Whead[j * 512 + 32 * i + lane];
    }
    #pragma unroll
    for (int j = 0; j < 15; ++j) {
        #pragma unroll
        for (int off = 16; off; off >>= 1)
            accv[j] += __shfl_xor_sync(0xffffffffu, accv[j], off);
    }
    if (lane == 0) {
        float lmax = -1e30f;
        #pragma unroll
        for (int j = 0; j < 5; ++j) {
            accv[j] += g_bhead[j];
            lmax = fmaxf(lmax, accv[j]);
        }
        float e[5], esum = 0.f;
        #pragma unroll
        for (int j = 0; j < 5; ++j) { e[j] = __expf(accv[j] - lmax); esum += e[j]; }
        float inv = 1.f / esum;
        float mu = 0.f, sg = 0.f;
        #pragma unroll
        for (int j = 0; j < 5; ++j) {
            float rho = e[j] * inv;
            mu += rho * (accv[5 + j] + g_bhead[5 + j]);
            sg += rho * __expf(accv[10 + j] + g_bhead[10 + j]);   // t = 0
        }
        float a = tanh_f(mu + sg * eps[(size_t)s * BATCH + gw]);
        g_angles[gw] = a;
        ((float2*)out)[(size_t)gw * SEG + s] = make_float2(a, 0.f);
    }
}

// ---------------- persistent kernel: all 512 steps ---------------------------
__global__ void __launch_bounds__(256, 1)
persist_kernel(const float* __restrict__ eps, float* __restrict__ out)
{
    extern __shared__ float smem[];
    __shared__ int s_tile;
    int epoch = 0;
    const int lane = threadIdx.x & 31;
    const int wg   = blockIdx.x * 8 + (threadIdx.x >> 5);   // global warp id

    for (int s = 0; s < SEG; ++s) {
        int pp = s & 1;

        // phase A: LSTM1 (dynamic 128x128 tiles, 512 total)
        for (;;) {
            __syncthreads();
            if (threadIdx.x == 0) s_tile = atomicAdd(&g_ctrs[2 * s], 1);
            __syncthreads();
            int t = s_tile;
            if (t >= 512) break;
            gemm_tile(2, pp, nullptr, nullptr, nullptr,
                      (t >> 4) * BM, (t & 15) * BN, smem);
        }
        gsync(epoch);

        // phase B: LSTM2 (K=1024)
        for (;;) {
            __syncthreads();
            if (threadIdx.x == 0) s_tile = atomicAdd(&g_ctrs[2 * s + 1], 1);
            __syncthreads();
            int t = s_tile;
            if (t >= 512) break;
            gemm_tile(3, pp, nullptr, nullptr, nullptr,
                      (t >> 4) * BM, (t & 15) * BN, smem);
        }
        gsync(epoch);

        // phase C: MDN heads (one warp per batch row)
        for (int row = wg; row < BATCH; row += NCTA * 8)
            head_row(eps, out, s, pp ^ 1, row, lane);
        gsync(epoch);
    }
}

// ---------------- launch ----------------------------------------------------
extern "C" void kernel_launch(void* const* d_in, const int* in_sizes, int n_in,
                              void* d_out, int out_size)
{
    const float* latent   = (const float*)d_in[0];
    const float* W_unpack = (const float*)d_in[1];
    const float* b_unpack = (const float*)d_in[2];
    const float* W_ih1    = (const float*)d_in[3];
    const float* W_hh1    = (const float*)d_in[4];
    const float* b_ih1    = (const float*)d_in[5];
    const float* b_hh1    = (const float*)d_in[6];
    const float* W_ih2    = (const float*)d_in[7];
    const float* W_hh2    = (const float*)d_in[8];
    const float* b_ih2    = (const float*)d_in[9];
    const float* b_hh2    = (const float*)d_in[10];
    const float* W_mu     = (const float*)d_in[11];
    const float* b_mu     = (const float*)d_in[12];
    const float* W_var    = (const float*)d_in[13];
    const float* b_var    = (const float*)d_in[14];
    const float* W_mix    = (const float*)d_in[15];
    const float* b_mix    = (const float*)d_in[16];
    const float* eps      = (const float*)d_in[17];
    float* out = (float*)d_out;

    const size_t shmem = (size_t)STG * STAGE_FLOATS * sizeof(float);   // 110592 B
    static int attr_done = 0;
    cudaFuncSetAttribute(gemm_kernel, cudaFuncAttributeMaxDynamicSharedMemorySize,
                         (int)shmem);
    cudaFuncSetAttribute(persist_kernel, cudaFuncAttributeMaxDynamicSharedMemorySize,
                         (int)shmem);
    (void)attr_done;

    zero_kernel<<<(BATCH * RNN + 255) / 256, 256>>>();
    reorder_kernel<<<GATES, 512>>>(W_ih1, W_hh1, b_ih1, b_hh1,
                                   W_ih2, W_hh2, b_ih2, b_hh2,
                                   W_mu, b_mu, W_var, b_var, W_mix, b_mix);

    // one-time: idea = tanh(latent @ W_unpack^T + b_unpack)
    gemm_kernel<<<dim3(CODE / BN, BATCH / BM), 256, shmem>>>(0, 0, latent, W_unpack, b_unpack);
    // one-time: base1 = idea @ W_ih1'[:, :512]^T + b_ih1 + b_hh1 (interleaved)
    gemm_kernel<<<dim3(GATES / BN, BATCH / BM), 256, shmem>>>(1, 0, nullptr, nullptr, nullptr);

    // all 512 steps in ONE persistent kernel (5 graph nodes total)
    persist_kernel<<<NCTA, 256, shmem>>>(eps, out);
}